// round 1
// baseline (speedup 1.0000x reference)
#include <cuda_runtime.h>
#include <math.h>

#define NN 50000
#define NE 800000
#define HD 128
#define OD 64

// Scratch (device globals: no allocation allowed in kernel_launch)
__device__ __align__(16) float g_bufA[NN * HD];
__device__ __align__(16) float g_bufB[NN * HD];
__device__ float g_dinv[NN];
__device__ int g_src[NE];
__device__ int g_dst[NE];
__device__ int g_is64;

// ---------------------------------------------------------------------------
// Edge index dtype detection: int64 little-endian stores 0 in odd 32-bit words
// (values < 50000). int32 random values make that astronomically unlikely.
// ---------------------------------------------------------------------------
__global__ void detect_kernel(const unsigned* __restrict__ p) {
    if (threadIdx.x == 0 && blockIdx.x == 0) {
        int is64 = 1;
        for (int w = 1; w < 64; w += 2) {
            if (p[w] != 0u) { is64 = 0; break; }
        }
        g_is64 = is64;
    }
}

// Convert edges to int32 arrays; also zero the degree accumulator.
__global__ void convert_zero_kernel(const void* __restrict__ ei) {
    int e = blockIdx.x * blockDim.x + threadIdx.x;
    if (e < NN) g_dinv[e] = 0.f;
    if (e < NE) {
        if (g_is64) {
            const long long* p = (const long long*)ei;
            g_src[e] = (int)p[e];
            g_dst[e] = (int)p[NE + e];
        } else {
            const int* p = (const int*)ei;
            g_src[e] = p[e];
            g_dst[e] = p[NE + e];
        }
    }
}

__global__ void count_kernel() {
    int e = blockIdx.x * blockDim.x + threadIdx.x;
    if (e < NE) atomicAdd(&g_dinv[g_dst[e]], 1.f);
}

// deg includes self-loop (+1); deg >= 1 so no zero guard needed.
__global__ void finalize_kernel() {
    int i = blockIdx.x * blockDim.x + threadIdx.x;
    if (i < NN) g_dinv[i] = rsqrtf(g_dinv[i] + 1.f);
}

// ---------------------------------------------------------------------------
// GEMM: out[N,NCOL] = act(A) @ W  (+ epilogues)
//   inb  != null : A elements become relu(A + inb[col])  (fused prior bias+relu)
//   EPI == 0     : write raw to out; write out2 = raw * dinv[row]^2 (self-loop init)
//   EPI == 1     : out = relu(raw + bias[col])
//   EPI == 2     : out = sigmoid(raw + bias[col])
// Block: 256 threads, 64 rows. W (128 x NCOL) + A tile (64 x 128) in smem.
// ---------------------------------------------------------------------------
template <int NCOL, int EPI>
__global__ void gemm_kernel(const float* __restrict__ A,
                            const float* __restrict__ inb,
                            const float* __restrict__ W,
                            const float* __restrict__ bias,
                            float* __restrict__ out,
                            float* __restrict__ out2) {
    extern __shared__ float sm[];
    float* Wsh = sm;                 // HD * NCOL floats
    float* Ash = sm + HD * NCOL;     // 64 * HD floats
    const int tid = threadIdx.x;
    const int row0 = blockIdx.x * 64;

    // Stage W
    float4* Wsh4 = (float4*)Wsh;
    const float4* W4 = (const float4*)W;
    #pragma unroll
    for (int i = tid; i < HD * NCOL / 4; i += 256) Wsh4[i] = W4[i];

    // Stage A tile (with fused bias+relu of the previous layer if requested)
    float4* Ash4 = (float4*)Ash;
    const float4* A4 = (const float4*)A;
    #pragma unroll
    for (int i = tid; i < 64 * 32; i += 256) {
        int r = i >> 5, q = i & 31;
        int grow = row0 + r;
        float4 v = make_float4(0.f, 0.f, 0.f, 0.f);
        if (grow < NN) {
            v = A4[grow * 32 + q];
            if (inb) {
                const float4 b = ((const float4*)inb)[q];
                v.x = fmaxf(v.x + b.x, 0.f);
                v.y = fmaxf(v.y + b.y, 0.f);
                v.z = fmaxf(v.z + b.z, 0.f);
                v.w = fmaxf(v.w + b.w, 0.f);
            }
        }
        Ash4[i] = v;
    }
    __syncthreads();

    constexpr int CG = NCOL / 8;        // column groups of 8
    constexpr int RPT = 64 * CG / 256;  // rows per thread
    const int cx = tid % CG;
    const int ry = (tid / CG) * RPT;

    float acc[RPT][8];
    #pragma unroll
    for (int r = 0; r < RPT; r++)
        #pragma unroll
        for (int c = 0; c < 8; c++) acc[r][c] = 0.f;

    #pragma unroll 4
    for (int k = 0; k < HD; k++) {
        float4 w0 = Wsh4[k * (NCOL / 4) + cx * 2];
        float4 w1 = Wsh4[k * (NCOL / 4) + cx * 2 + 1];
        #pragma unroll
        for (int r = 0; r < RPT; r++) {
            float a = Ash[(ry + r) * HD + k];
            acc[r][0] = fmaf(a, w0.x, acc[r][0]);
            acc[r][1] = fmaf(a, w0.y, acc[r][1]);
            acc[r][2] = fmaf(a, w0.z, acc[r][2]);
            acc[r][3] = fmaf(a, w0.w, acc[r][3]);
            acc[r][4] = fmaf(a, w1.x, acc[r][4]);
            acc[r][5] = fmaf(a, w1.y, acc[r][5]);
            acc[r][6] = fmaf(a, w1.z, acc[r][6]);
            acc[r][7] = fmaf(a, w1.w, acc[r][7]);
        }
    }

    float bb[8];
    if (EPI != 0) {
        #pragma unroll
        for (int c = 0; c < 8; c++) bb[c] = bias[cx * 8 + c];
    }

    #pragma unroll
    for (int r = 0; r < RPT; r++) {
        int grow = row0 + ry + r;
        if (grow >= NN) continue;
        float vals[8];
        #pragma unroll
        for (int c = 0; c < 8; c++) {
            float v = acc[r][c];
            if (EPI == 1) v = fmaxf(v + bb[c], 0.f);
            if (EPI == 2) { v += bb[c]; v = 1.f / (1.f + expf(-v)); }
            vals[c] = v;
        }
        float4* o4 = (float4*)(out + grow * NCOL + cx * 8);
        o4[0] = make_float4(vals[0], vals[1], vals[2], vals[3]);
        o4[1] = make_float4(vals[4], vals[5], vals[6], vals[7]);
        if (EPI == 0) {
            float d = g_dinv[grow];
            float d2 = d * d;
            float4* o24 = (float4*)(out2 + grow * NCOL + cx * 8);
            o24[0] = make_float4(vals[0] * d2, vals[1] * d2, vals[2] * d2, vals[3] * d2);
            o24[1] = make_float4(vals[4] * d2, vals[5] * d2, vals[6] * d2, vals[7] * d2);
        }
    }
}

// ---------------------------------------------------------------------------
// Edge scatter: one warp per edge. lane-strided float4 gather of t[src],
// scaled by dinv[src]*dinv[dst], vector-reduced into out[dst].
// ---------------------------------------------------------------------------
__global__ void scatter_kernel(const float* __restrict__ t, float* __restrict__ out) {
    int gid = blockIdx.x * blockDim.x + threadIdx.x;
    int e = gid >> 5;
    int lane = gid & 31;
    if (e >= NE) return;
    int s = g_src[e];
    int d = g_dst[e];
    float norm = g_dinv[s] * g_dinv[d];
    float4 v = ((const float4*)(t + s * HD))[lane];
    float* dp = out + d * HD + lane * 4;
    asm volatile("red.global.add.v4.f32 [%0], {%1, %2, %3, %4};"
                 :: "l"(dp), "f"(v.x * norm), "f"(v.y * norm),
                    "f"(v.z * norm), "f"(v.w * norm)
                 : "memory");
}

// ---------------------------------------------------------------------------
extern "C" void kernel_launch(void* const* d_in, const int* in_sizes, int n_in,
                              void* d_out, int out_size) {
    const float* x   = (const float*)d_in[0];
    const void*  ei  = d_in[1];
    const float* W1  = (const float*)d_in[2];
    const float* b1  = (const float*)d_in[3];
    const float* W2  = (const float*)d_in[4];
    const float* b2  = (const float*)d_in[5];
    const float* W3  = (const float*)d_in[6];
    const float* b3  = (const float*)d_in[7];
    const float* Wd1 = (const float*)d_in[8];
    const float* bd1 = (const float*)d_in[9];
    const float* Wd2 = (const float*)d_in[10];
    const float* bd2 = (const float*)d_in[11];
    float* out = (float*)d_out;

    float *bufA, *bufB;
    cudaGetSymbolAddress((void**)&bufA, g_bufA);
    cudaGetSymbolAddress((void**)&bufB, g_bufB);

    const int smem128 = (HD * HD + 64 * HD) * (int)sizeof(float);  // 96 KB
    const int smem64  = (HD * OD + 64 * HD) * (int)sizeof(float);  // 64 KB
    cudaFuncSetAttribute((const void*)gemm_kernel<128, 0>,
                         cudaFuncAttributeMaxDynamicSharedMemorySize, smem128);
    cudaFuncSetAttribute((const void*)gemm_kernel<128, 1>,
                         cudaFuncAttributeMaxDynamicSharedMemorySize, smem128);
    cudaFuncSetAttribute((const void*)gemm_kernel<64, 2>,
                         cudaFuncAttributeMaxDynamicSharedMemorySize, smem64);

    const int gblocks = (NN + 63) / 64;        // 782
    const int eblocks = (NE + 255) / 256;      // 3125
    const int sblocks = (NE * 32) / 256;       // 100000

    // Degree / normalization
    detect_kernel<<<1, 32>>>((const unsigned*)ei);
    convert_zero_kernel<<<eblocks, 256>>>(ei);
    count_kernel<<<eblocks, 256>>>();
    finalize_kernel<<<(NN + 255) / 256, 256>>>();

    // Conv layer 1: bufA = x@W1 ; bufB = self-loop init ; scatter edges into bufB
    gemm_kernel<128, 0><<<gblocks, 256, smem128>>>(x, nullptr, W1, nullptr, bufA, bufB);
    scatter_kernel<<<sblocks, 256>>>(bufA, bufB);

    // Conv layer 2 (bias+relu of layer 1 fused into A-load)
    gemm_kernel<128, 0><<<gblocks, 256, smem128>>>(bufB, b1, W2, nullptr, bufA, bufB);
    scatter_kernel<<<sblocks, 256>>>(bufA, bufB);

    // Conv layer 3
    gemm_kernel<128, 0><<<gblocks, 256, smem128>>>(bufB, b2, W3, nullptr, bufA, bufB);
    scatter_kernel<<<sblocks, 256>>>(bufA, bufB);

    // Dense 1: bufA = relu(relu(bufB + b3) @ Wd1 + bd1)
    gemm_kernel<128, 1><<<gblocks, 256, smem128>>>(bufB, b3, Wd1, bd1, bufA, nullptr);

    // Dense 2: out = sigmoid(bufA @ Wd2 + bd2)
    gemm_kernel<64, 2><<<gblocks, 256, smem64>>>(bufA, nullptr, Wd2, bd2, out, nullptr);
}

// round 2
// speedup vs baseline: 1.0001x; 1.0001x over previous
#include <cuda_runtime.h>
#include <math.h>

#define NN 50000
#define NE 800000
#define HD 128
#define OD 64

// Scratch (device globals: no allocation allowed in kernel_launch)
__device__ __align__(16) float g_bufA[NN * HD];
__device__ __align__(16) float g_bufB[NN * HD];
__device__ float g_dinv[NN];
__device__ int g_src[NE];
__device__ int g_dst[NE];
__device__ int g_is64;

typedef unsigned long long ull;

// Packed fp32x2 FMA (Blackwell, PTX-only path -> SASS FFMA2)
__device__ __forceinline__ void ffma2(ull& d, ull a, ull b) {
    asm("fma.rn.f32x2 %0, %1, %2, %0;" : "+l"(d) : "l"(a), "l"(b));
}
__device__ __forceinline__ ull splat2(float a) {
    ull r;
    asm("mov.b64 %0, {%1, %1};" : "=l"(r) : "f"(a));
    return r;
}

// ---------------------------------------------------------------------------
// Preprocess pass 1: zero-init degrees to 1.0 (self-loop) + detect edge dtype.
// int64 little-endian has 0 in odd 32-bit words (all values < 50000).
// ---------------------------------------------------------------------------
__global__ void pre_kernel(const unsigned* __restrict__ p) {
    int i = blockIdx.x * blockDim.x + threadIdx.x;
    if (i < NN) g_dinv[i] = 1.f;  // self-loop pre-counted
    if (i == 0) {
        int is64 = 1;
        for (int w = 1; w < 128; w += 2)
            if (p[w] != 0u) { is64 = 0; break; }
        g_is64 = is64;
    }
}

// Preprocess pass 2: convert edges to int32 + accumulate in-degree.
__global__ void convert_count_kernel(const void* __restrict__ ei) {
    int e = blockIdx.x * blockDim.x + threadIdx.x;
    if (e >= NE) return;
    int s, d;
    if (g_is64) {
        const long long* p = (const long long*)ei;
        s = (int)p[e];
        d = (int)p[NE + e];
    } else {
        const int* p = (const int*)ei;
        s = p[e];
        d = p[NE + e];
    }
    g_src[e] = s;
    g_dst[e] = d;
    atomicAdd(&g_dinv[d], 1.f);
}

__global__ void finalize_kernel() {
    int i = blockIdx.x * blockDim.x + threadIdx.x;
    if (i < NN) g_dinv[i] = rsqrtf(g_dinv[i]);  // deg >= 1 always
}

// ---------------------------------------------------------------------------
// Conv GEMM: raw = act(A) @ W (act = relu(.+inb) if inb) ; out = raw ;
// out2 = raw * dinv[row]^2 (self-loop contribution, initializes the scatter
// accumulator). 256 threads, 64-row tile, FFMA2 mainloop (4 rows x 8 cols).
// ---------------------------------------------------------------------------
__global__ void conv_gemm_kernel(const float* __restrict__ A,
                                 const float* __restrict__ inb,
                                 const float* __restrict__ W,
                                 float* __restrict__ out,
                                 float* __restrict__ out2) {
    extern __shared__ float sm[];
    float* Wsh = sm;              // 128*128
    float* Ash = sm + HD * HD;    // 64*128
    const int tid = threadIdx.x;
    const int row0 = blockIdx.x * 64;

    // Stage W
    {
        float4* Wsh4 = (float4*)Wsh;
        const float4* W4 = (const float4*)W;
        #pragma unroll
        for (int i = tid; i < HD * HD / 4; i += 256) Wsh4[i] = W4[i];
    }
    // Stage A tile (fused prev-layer bias+relu)
    {
        float4* Ash4 = (float4*)Ash;
        const float4* A4 = (const float4*)A;
        #pragma unroll
        for (int i = tid; i < 64 * 32; i += 256) {
            int r = i >> 5, q = i & 31;
            int grow = row0 + r;
            float4 v = make_float4(0.f, 0.f, 0.f, 0.f);
            if (grow < NN) {
                v = A4[grow * 32 + q];
                if (inb) {
                    const float4 b = ((const float4*)inb)[q];
                    v.x = fmaxf(v.x + b.x, 0.f);
                    v.y = fmaxf(v.y + b.y, 0.f);
                    v.z = fmaxf(v.z + b.z, 0.f);
                    v.w = fmaxf(v.w + b.w, 0.f);
                }
            }
            Ash4[i] = v;
        }
    }
    __syncthreads();

    const ull* Wsh2 = (const ull*)Wsh;
    const int cx = tid & 15;          // 16 column groups of 8 cols (4 f32x2 pairs)
    const int ry = (tid >> 4) << 2;   // 4 rows per thread

    ull acc[4][4];
    #pragma unroll
    for (int r = 0; r < 4; r++)
        #pragma unroll
        for (int p = 0; p < 4; p++) acc[r][p] = 0ull;

    #pragma unroll 4
    for (int k = 0; k < HD; k++) {
        ulonglong2 wa = *(const ulonglong2*)(Wsh2 + k * 64 + cx * 4);
        ulonglong2 wb = *(const ulonglong2*)(Wsh2 + k * 64 + cx * 4 + 2);
        #pragma unroll
        for (int r = 0; r < 4; r++) {
            ull a2 = splat2(Ash[(ry + r) * HD + k]);
            ffma2(acc[r][0], a2, wa.x);
            ffma2(acc[r][1], a2, wa.y);
            ffma2(acc[r][2], a2, wb.x);
            ffma2(acc[r][3], a2, wb.y);
        }
    }

    #pragma unroll
    for (int r = 0; r < 4; r++) {
        int grow = row0 + ry + r;
        if (grow >= NN) continue;
        float2 p0 = *(float2*)&acc[r][0];
        float2 p1 = *(float2*)&acc[r][1];
        float2 p2 = *(float2*)&acc[r][2];
        float2 p3 = *(float2*)&acc[r][3];
        float4* o4 = (float4*)(out + grow * HD + cx * 8);
        o4[0] = make_float4(p0.x, p0.y, p1.x, p1.y);
        o4[1] = make_float4(p2.x, p2.y, p3.x, p3.y);
        float d = g_dinv[grow];
        float d2 = d * d;
        float4* o24 = (float4*)(out2 + grow * HD + cx * 8);
        o24[0] = make_float4(p0.x * d2, p0.y * d2, p1.x * d2, p1.y * d2);
        o24[1] = make_float4(p2.x * d2, p2.y * d2, p3.x * d2, p3.y * d2);
    }
}

// ---------------------------------------------------------------------------
// Fused dense head: out = sigmoid( relu( relu(A+b3) @ Wd1 + bd1 ) @ Wd2 + bd2 )
// Wd1 (64KB) + Wd2 (32KB) + A tile (32KB) all staged in 128KB smem.
// ---------------------------------------------------------------------------
__global__ void dense_kernel(const float* __restrict__ A,
                             const float* __restrict__ b3,
                             const float* __restrict__ Wd1,
                             const float* __restrict__ bd1,
                             const float* __restrict__ Wd2,
                             const float* __restrict__ bd2,
                             float* __restrict__ out) {
    extern __shared__ float sm[];
    float* W1sh = sm;               // 16384
    float* W2sh = sm + 16384;       // 8192
    float* Ash  = sm + 24576;       // 8192
    const int tid = threadIdx.x;
    const int row0 = blockIdx.x * 64;

    {
        float4* d4 = (float4*)W1sh;
        const float4* s4 = (const float4*)Wd1;
        #pragma unroll
        for (int i = tid; i < HD * HD / 4; i += 256) d4[i] = s4[i];
        float4* d24 = (float4*)W2sh;
        const float4* s24 = (const float4*)Wd2;
        #pragma unroll
        for (int i = tid; i < HD * OD / 4; i += 256) d24[i] = s24[i];
        float4* Ash4 = (float4*)Ash;
        const float4* A4 = (const float4*)A;
        #pragma unroll
        for (int i = tid; i < 64 * 32; i += 256) {
            int r = i >> 5, q = i & 31;
            int grow = row0 + r;
            float4 v = make_float4(0.f, 0.f, 0.f, 0.f);
            if (grow < NN) {
                v = A4[grow * 32 + q];
                const float4 b = ((const float4*)b3)[q];
                v.x = fmaxf(v.x + b.x, 0.f);
                v.y = fmaxf(v.y + b.y, 0.f);
                v.z = fmaxf(v.z + b.z, 0.f);
                v.w = fmaxf(v.w + b.w, 0.f);
            }
            Ash4[i] = v;
        }
    }
    __syncthreads();

    // ---- GEMM1: h1 = relu(A @ Wd1 + bd1), held in registers ----
    const ull* W1sh2 = (const ull*)W1sh;
    const int cx = tid & 15;
    const int ry = (tid >> 4) << 2;

    ull acc[4][4];
    #pragma unroll
    for (int r = 0; r < 4; r++)
        #pragma unroll
        for (int p = 0; p < 4; p++) acc[r][p] = 0ull;

    #pragma unroll 4
    for (int k = 0; k < HD; k++) {
        ulonglong2 wa = *(const ulonglong2*)(W1sh2 + k * 64 + cx * 4);
        ulonglong2 wb = *(const ulonglong2*)(W1sh2 + k * 64 + cx * 4 + 2);
        #pragma unroll
        for (int r = 0; r < 4; r++) {
            ull a2 = splat2(Ash[(ry + r) * HD + k]);
            ffma2(acc[r][0], a2, wa.x);
            ffma2(acc[r][1], a2, wa.y);
            ffma2(acc[r][2], a2, wb.x);
            ffma2(acc[r][3], a2, wb.y);
        }
    }

    float h[4][8];
    {
        float bb[8];
        #pragma unroll
        for (int c = 0; c < 8; c++) bb[c] = bd1[cx * 8 + c];
        #pragma unroll
        for (int r = 0; r < 4; r++) {
            float2 p0 = *(float2*)&acc[r][0];
            float2 p1 = *(float2*)&acc[r][1];
            float2 p2 = *(float2*)&acc[r][2];
            float2 p3 = *(float2*)&acc[r][3];
            h[r][0] = fmaxf(p0.x + bb[0], 0.f);
            h[r][1] = fmaxf(p0.y + bb[1], 0.f);
            h[r][2] = fmaxf(p1.x + bb[2], 0.f);
            h[r][3] = fmaxf(p1.y + bb[3], 0.f);
            h[r][4] = fmaxf(p2.x + bb[4], 0.f);
            h[r][5] = fmaxf(p2.y + bb[5], 0.f);
            h[r][6] = fmaxf(p3.x + bb[6], 0.f);
            h[r][7] = fmaxf(p3.y + bb[7], 0.f);
        }
    }

    __syncthreads();   // all GEMM1 reads of Ash done
    #pragma unroll
    for (int r = 0; r < 4; r++)
        #pragma unroll
        for (int c = 0; c < 8; c++)
            Ash[(ry + r) * HD + cx * 8 + c] = h[r][c];
    __syncthreads();

    // ---- GEMM2: out = sigmoid(h1 @ Wd2 + bd2) ----
    const ull* W2sh2 = (const ull*)W2sh;
    const int cx2 = tid & 7;          // 8 column groups of 8 (of 64 cols)
    const int ry2 = (tid >> 3) << 1;  // 2 rows per thread

    ull acc2[2][4];
    #pragma unroll
    for (int r = 0; r < 2; r++)
        #pragma unroll
        for (int p = 0; p < 4; p++) acc2[r][p] = 0ull;

    #pragma unroll 4
    for (int k = 0; k < HD; k++) {
        ulonglong2 wa = *(const ulonglong2*)(W2sh2 + k * 32 + cx2 * 4);
        ulonglong2 wb = *(const ulonglong2*)(W2sh2 + k * 32 + cx2 * 4 + 2);
        #pragma unroll
        for (int r = 0; r < 2; r++) {
            ull a2 = splat2(Ash[(ry2 + r) * HD + k]);
            ffma2(acc2[r][0], a2, wa.x);
            ffma2(acc2[r][1], a2, wa.y);
            ffma2(acc2[r][2], a2, wb.x);
            ffma2(acc2[r][3], a2, wb.y);
        }
    }

    float bb2[8];
    #pragma unroll
    for (int c = 0; c < 8; c++) bb2[c] = bd2[cx2 * 8 + c];
    #pragma unroll
    for (int r = 0; r < 2; r++) {
        int grow = row0 + ry2 + r;
        if (grow >= NN) continue;
        float2 q0 = *(float2*)&acc2[r][0];
        float2 q1 = *(float2*)&acc2[r][1];
        float2 q2 = *(float2*)&acc2[r][2];
        float2 q3 = *(float2*)&acc2[r][3];
        float v[8] = {q0.x, q0.y, q1.x, q1.y, q2.x, q2.y, q3.x, q3.y};
        #pragma unroll
        for (int c = 0; c < 8; c++)
            v[c] = 1.f / (1.f + __expf(-(v[c] + bb2[c])));
        float4* o4 = (float4*)(out + grow * OD + cx2 * 8);
        o4[0] = make_float4(v[0], v[1], v[2], v[3]);
        o4[1] = make_float4(v[4], v[5], v[6], v[7]);
    }
}

// ---------------------------------------------------------------------------
// Edge scatter: one warp per edge. lane-strided float4 gather of t[src],
// scaled by dinv[src]*dinv[dst], vector-reduced into out[dst].
// ---------------------------------------------------------------------------
__global__ void scatter_kernel(const float* __restrict__ t, float* __restrict__ out) {
    int gid = blockIdx.x * blockDim.x + threadIdx.x;
    int e = gid >> 5;
    int lane = gid & 31;
    if (e >= NE) return;
    int s = g_src[e];
    int d = g_dst[e];
    float norm = g_dinv[s] * g_dinv[d];
    float4 v = ((const float4*)(t + s * HD))[lane];
    float* dp = out + d * HD + lane * 4;
    asm volatile("red.global.add.v4.f32 [%0], {%1, %2, %3, %4};"
                 :: "l"(dp), "f"(v.x * norm), "f"(v.y * norm),
                    "f"(v.z * norm), "f"(v.w * norm)
                 : "memory");
}

// ---------------------------------------------------------------------------
extern "C" void kernel_launch(void* const* d_in, const int* in_sizes, int n_in,
                              void* d_out, int out_size) {
    const float* x   = (const float*)d_in[0];
    const void*  ei  = d_in[1];
    const float* W1  = (const float*)d_in[2];
    const float* b1  = (const float*)d_in[3];
    const float* W2  = (const float*)d_in[4];
    const float* b2  = (const float*)d_in[5];
    const float* W3  = (const float*)d_in[6];
    const float* b3  = (const float*)d_in[7];
    const float* Wd1 = (const float*)d_in[8];
    const float* bd1 = (const float*)d_in[9];
    const float* Wd2 = (const float*)d_in[10];
    const float* bd2 = (const float*)d_in[11];
    float* out = (float*)d_out;

    float *bufA, *bufB;
    cudaGetSymbolAddress((void**)&bufA, g_bufA);
    cudaGetSymbolAddress((void**)&bufB, g_bufB);

    const int smem_conv  = (HD * HD + 64 * HD) * (int)sizeof(float);            // 96 KB
    const int smem_dense = (HD * HD + HD * OD + 64 * HD) * (int)sizeof(float);  // 128 KB
    cudaFuncSetAttribute((const void*)conv_gemm_kernel,
                         cudaFuncAttributeMaxDynamicSharedMemorySize, smem_conv);
    cudaFuncSetAttribute((const void*)dense_kernel,
                         cudaFuncAttributeMaxDynamicSharedMemorySize, smem_dense);

    const int gblocks = (NN + 63) / 64;        // 782
    const int eblocks = (NE + 255) / 256;      // 3125
    const int nblocks = (NN + 255) / 256;      // 196
    const int sblocks = (NE * 32) / 256;       // 100000

    // Degree / normalization (2 edge passes instead of 3)
    pre_kernel<<<nblocks, 256>>>((const unsigned*)ei);
    convert_count_kernel<<<eblocks, 256>>>(ei);
    finalize_kernel<<<nblocks, 256>>>();

    // Conv layer 1: bufA = x@W1 ; bufB = self-loop init ; scatter edges into bufB
    conv_gemm_kernel<<<gblocks, 256, smem_conv>>>(x, nullptr, W1, bufA, bufB);
    scatter_kernel<<<sblocks, 256>>>(bufA, bufB);

    // Conv layer 2 (bias+relu of layer 1 fused into A-load)
    conv_gemm_kernel<<<gblocks, 256, smem_conv>>>(bufB, b1, W2, bufA, bufB);
    scatter_kernel<<<sblocks, 256>>>(bufA, bufB);

    // Conv layer 3
    conv_gemm_kernel<<<gblocks, 256, smem_conv>>>(bufB, b2, W3, bufA, bufB);
    scatter_kernel<<<sblocks, 256>>>(bufA, bufB);

    // Fused dense head
    dense_kernel<<<gblocks, 256, smem_dense>>>(bufB, b3, Wd1, bd1, Wd2, bd2, out);
}

// round 3
// speedup vs baseline: 1.2665x; 1.2665x over previous
#include <cuda_runtime.h>
#include <math.h>

#define NN 50000
#define NE 800000
#define HD 128
#define OD 64

typedef unsigned long long ull;

// Scratch (device globals: no allocation allowed in kernel_launch)
__device__ __align__(16) float g_bufA[NN * HD];
__device__ __align__(16) float g_bufB[NN * HD];
__device__ float g_dinv[NN];
__device__ int g_count[NN];
__device__ int g_rowstart[NN + 1];
__device__ int g_cursor[NN];
__device__ int g_src[NE];
__device__ int g_dst[NE];
__device__ int g_csrc[NE];
__device__ int g_is64;

// Packed fp32x2 FMA (Blackwell FFMA2, PTX-only path)
__device__ __forceinline__ void ffma2(ull& d, ull a, ull b) {
    asm("fma.rn.f32x2 %0, %1, %2, %0;" : "+l"(d) : "l"(a), "l"(b));
}

// ---------------------------------------------------------------------------
// Preprocess 1: zero degree counts + detect edge dtype (int64 LE has zero odd
// 32-bit words since all values < 50000).
// ---------------------------------------------------------------------------
__global__ void pre_kernel(const unsigned* __restrict__ p) {
    int i = blockIdx.x * blockDim.x + threadIdx.x;
    if (i < NN) g_count[i] = 0;
    if (i == 0) {
        int is64 = 1;
        for (int w = 1; w < 128; w += 2)
            if (p[w] != 0u) { is64 = 0; break; }
        g_is64 = is64;
    }
}

// Preprocess 2: convert edges to int32 + in-degree histogram.
__global__ void convert_count_kernel(const void* __restrict__ ei) {
    int e = blockIdx.x * blockDim.x + threadIdx.x;
    if (e >= NE) return;
    int s, d;
    if (g_is64) {
        const long long* p = (const long long*)ei;
        s = (int)p[e];
        d = (int)p[NE + e];
    } else {
        const int* p = (const int*)ei;
        s = p[e];
        d = p[NE + e];
    }
    g_src[e] = s;
    g_dst[e] = d;
    atomicAdd(&g_count[d], 1);
}

// Preprocess 3: single-block exclusive scan of counts -> rowstart/cursor,
// plus dinv = rsqrt(deg + 1) (self-loop included).
__global__ void scan_kernel() {
    __shared__ int partial[1024];
    const int tid = threadIdx.x;
    const int CH = (NN + 1023) / 1024;  // 49
    const int i0 = tid * CH;
    const int i1 = min(i0 + CH, NN);

    int sum = 0;
    for (int i = i0; i < i1; i++) sum += g_count[i];
    partial[tid] = sum;
    __syncthreads();
    for (int off = 1; off < 1024; off <<= 1) {
        int v = (tid >= off) ? partial[tid - off] : 0;
        __syncthreads();
        partial[tid] += v;
        __syncthreads();
    }
    int run = (tid > 0) ? partial[tid - 1] : 0;
    for (int i = i0; i < i1; i++) {
        g_rowstart[i] = run;
        g_cursor[i] = run;
        int c = g_count[i];
        run += c;
        g_dinv[i] = rsqrtf((float)c + 1.f);
    }
    if (tid == 0) g_rowstart[NN] = NE;
}

// Preprocess 4: bucket-fill CSR source lists.
__global__ void fill_kernel() {
    int e = blockIdx.x * blockDim.x + threadIdx.x;
    if (e >= NE) return;
    int pos = atomicAdd(&g_cursor[g_dst[e]], 1);
    g_csrc[pos] = g_src[e];
}

// ---------------------------------------------------------------------------
// Conv GEMM: out = act(A) @ W, act = relu(.+inb) if inb.
// 512 threads, 128-row tile. k-pair packed FFMA2: W staged in smem as
// (W[2k][c], W[2k+1][c]) f32x2 pairs; A read as float2 over (2k, 2k+1).
// acc.x holds even-k partial, acc.y odd-k; horizontal add at the end.
// Thread owns 4 rows x 8 interleaved cols (col = cx + 16j) -> conflict-free.
// ---------------------------------------------------------------------------
__global__ void __launch_bounds__(512, 1)
conv_gemm_kernel(const float* __restrict__ A,
                 const float* __restrict__ inb,
                 const float* __restrict__ W,
                 float* __restrict__ out) {
    extern __shared__ float sm[];
    float* Wp  = sm;             // 64 kpairs * 128 cols * 2 = 16384 floats
    float* Ash = sm + 16384;     // 128 rows * 128 k
    const int tid = threadIdx.x;
    const int row0 = blockIdx.x * 128;

    // Stage W into pair layout: ull index kp*128 + c
    for (int i = tid; i < 4096; i += 512) {
        int k = i >> 5;           // source row
        int c4 = i & 31;          // float4 col group
        float4 v = ((const float4*)W)[i];
        float* base = Wp + (k >> 1) * 256 + c4 * 8 + (k & 1);
        base[0] = v.x; base[2] = v.y; base[4] = v.z; base[6] = v.w;
    }
    // Stage A tile (fused prev-layer bias+relu)
    for (int i = tid; i < 128 * 32; i += 512) {
        int r = i >> 5, q = i & 31;
        int grow = row0 + r;
        float4 v = make_float4(0.f, 0.f, 0.f, 0.f);
        if (grow < NN) {
            v = ((const float4*)A)[grow * 32 + q];
            if (inb) {
                const float4 b = ((const float4*)inb)[q];
                v.x = fmaxf(v.x + b.x, 0.f);
                v.y = fmaxf(v.y + b.y, 0.f);
                v.z = fmaxf(v.z + b.z, 0.f);
                v.w = fmaxf(v.w + b.w, 0.f);
            }
        }
        ((float4*)Ash)[i] = v;
    }
    __syncthreads();

    const ull* Wp2 = (const ull*)Wp;
    const int cx = tid & 15;
    const int ry = (tid >> 4) * 4;

    ull acc[4][8];
    #pragma unroll
    for (int r = 0; r < 4; r++)
        #pragma unroll
        for (int j = 0; j < 8; j++) acc[r][j] = 0ull;

    #pragma unroll 2
    for (int kp = 0; kp < 64; kp++) {
        ull w[8];
        #pragma unroll
        for (int j = 0; j < 8; j++) w[j] = Wp2[kp * 128 + cx + 16 * j];
        #pragma unroll
        for (int r = 0; r < 4; r++) {
            ull a2 = *(const ull*)(Ash + (ry + r) * 128 + kp * 2);
            #pragma unroll
            for (int j = 0; j < 8; j++) ffma2(acc[r][j], a2, w[j]);
        }
    }

    #pragma unroll
    for (int r = 0; r < 4; r++) {
        int grow = row0 + ry + r;
        if (grow >= NN) continue;
        #pragma unroll
        for (int j = 0; j < 8; j++) {
            float2 p = *(float2*)&acc[r][j];
            out[grow * HD + cx + 16 * j] = p.x + p.y;
        }
    }
}

// ---------------------------------------------------------------------------
// CSR gather aggregation: one warp per destination node.
// acc initialized with self-loop term t[d]*dinv[d]^2; edges accumulated with
// norm = dinv[s]*dinv[d]; single coalesced write. 1-deep src prefetch.
// ---------------------------------------------------------------------------
__global__ void gather_kernel(const float* __restrict__ t,
                              float* __restrict__ out) {
    int gid = blockIdx.x * blockDim.x + threadIdx.x;
    int d = gid >> 5;
    int lane = gid & 31;
    if (d >= NN) return;

    float dd = g_dinv[d];
    float4 acc = ((const float4*)(t + d * HD))[lane];
    float s2 = dd * dd;
    acc.x *= s2; acc.y *= s2; acc.z *= s2; acc.w *= s2;

    int beg = g_rowstart[d];
    int end = g_rowstart[d + 1];
    int s = (beg < end) ? g_csrc[beg] : 0;
    for (int j = beg; j < end; j++) {
        int snext = (j + 1 < end) ? g_csrc[j + 1] : 0;
        float nm = dd * g_dinv[s];
        float4 v = ((const float4*)(t + s * HD))[lane];
        acc.x = fmaf(v.x, nm, acc.x);
        acc.y = fmaf(v.y, nm, acc.y);
        acc.z = fmaf(v.z, nm, acc.z);
        acc.w = fmaf(v.w, nm, acc.w);
        s = snext;
    }
    ((float4*)(out + d * HD))[lane] = acc;
}

// ---------------------------------------------------------------------------
// Fused dense head: out = sigmoid( relu( relu(A+b3) @ Wd1 + bd1 ) @ Wd2 + bd2 )
// Same k-pair FFMA2 scheme for both GEMMs; h1 round-trips through Ash.
// ---------------------------------------------------------------------------
__global__ void __launch_bounds__(512, 1)
dense_kernel(const float* __restrict__ A,
             const float* __restrict__ b3,
             const float* __restrict__ Wd1,
             const float* __restrict__ bd1,
             const float* __restrict__ Wd2,
             const float* __restrict__ bd2,
             float* __restrict__ out) {
    extern __shared__ float sm[];
    float* W1p = sm;             // 16384
    float* W2p = sm + 16384;     // 8192 (64 kpairs * 64 cols * 2)
    float* Ash = sm + 24576;     // 16384
    const int tid = threadIdx.x;
    const int row0 = blockIdx.x * 128;

    for (int i = tid; i < 4096; i += 512) {
        int k = i >> 5, c4 = i & 31;
        float4 v = ((const float4*)Wd1)[i];
        float* base = W1p + (k >> 1) * 256 + c4 * 8 + (k & 1);
        base[0] = v.x; base[2] = v.y; base[4] = v.z; base[6] = v.w;
    }
    for (int i = tid; i < 2048; i += 512) {
        int k = i >> 4, c4 = i & 15;
        float4 v = ((const float4*)Wd2)[i];
        float* base = W2p + (k >> 1) * 128 + c4 * 8 + (k & 1);
        base[0] = v.x; base[2] = v.y; base[4] = v.z; base[6] = v.w;
    }
    for (int i = tid; i < 128 * 32; i += 512) {
        int r = i >> 5, q = i & 31;
        int grow = row0 + r;
        float4 v = make_float4(0.f, 0.f, 0.f, 0.f);
        if (grow < NN) {
            v = ((const float4*)A)[grow * 32 + q];
            const float4 b = ((const float4*)b3)[q];
            v.x = fmaxf(v.x + b.x, 0.f);
            v.y = fmaxf(v.y + b.y, 0.f);
            v.z = fmaxf(v.z + b.z, 0.f);
            v.w = fmaxf(v.w + b.w, 0.f);
        }
        ((float4*)Ash)[i] = v;
    }
    __syncthreads();

    // ---- GEMM1: h1 = relu(A @ Wd1 + bd1) ----
    const ull* W1p2 = (const ull*)W1p;
    const int cx = tid & 15;
    const int ry = (tid >> 4) * 4;

    ull acc[4][8];
    #pragma unroll
    for (int r = 0; r < 4; r++)
        #pragma unroll
        for (int j = 0; j < 8; j++) acc[r][j] = 0ull;

    #pragma unroll 2
    for (int kp = 0; kp < 64; kp++) {
        ull w[8];
        #pragma unroll
        for (int j = 0; j < 8; j++) w[j] = W1p2[kp * 128 + cx + 16 * j];
        #pragma unroll
        for (int r = 0; r < 4; r++) {
            ull a2 = *(const ull*)(Ash + (ry + r) * 128 + kp * 2);
            #pragma unroll
            for (int j = 0; j < 8; j++) ffma2(acc[r][j], a2, w[j]);
        }
    }

    float h[4][8];
    #pragma unroll
    for (int r = 0; r < 4; r++)
        #pragma unroll
        for (int j = 0; j < 8; j++) {
            float2 p = *(float2*)&acc[r][j];
            h[r][j] = fmaxf(p.x + p.y + bd1[cx + 16 * j], 0.f);
        }

    __syncthreads();
    #pragma unroll
    for (int r = 0; r < 4; r++)
        #pragma unroll
        for (int j = 0; j < 8; j++)
            Ash[(ry + r) * 128 + cx + 16 * j] = h[r][j];
    __syncthreads();

    // ---- GEMM2: out = sigmoid(h1 @ Wd2 + bd2) ----
    const ull* W2p2 = (const ull*)W2p;
    const int cx2 = tid & 7;            // cols = cx2 + 8j, j=0..7 (64 cols)
    const int ry2 = (tid >> 3) * 2;     // 2 rows per thread, 128 rows

    ull acc2[2][8];
    #pragma unroll
    for (int r = 0; r < 2; r++)
        #pragma unroll
        for (int j = 0; j < 8; j++) acc2[r][j] = 0ull;

    #pragma unroll 2
    for (int kp = 0; kp < 64; kp++) {
        ull w[8];
        #pragma unroll
        for (int j = 0; j < 8; j++) w[j] = W2p2[kp * 64 + cx2 + 8 * j];
        #pragma unroll
        for (int r = 0; r < 2; r++) {
            ull a2 = *(const ull*)(Ash + (ry2 + r) * 128 + kp * 2);
            #pragma unroll
            for (int j = 0; j < 8; j++) ffma2(acc2[r][j], a2, w[j]);
        }
    }

    #pragma unroll
    for (int r = 0; r < 2; r++) {
        int grow = row0 + ry2 + r;
        if (grow >= NN) continue;
        #pragma unroll
        for (int j = 0; j < 8; j++) {
            float2 p = *(float2*)&acc2[r][j];
            float v = p.x + p.y + bd2[cx2 + 8 * j];
            out[grow * OD + cx2 + 8 * j] = 1.f / (1.f + __expf(-v));
        }
    }
}

// ---------------------------------------------------------------------------
extern "C" void kernel_launch(void* const* d_in, const int* in_sizes, int n_in,
                              void* d_out, int out_size) {
    const float* x   = (const float*)d_in[0];
    const void*  ei  = d_in[1];
    const float* W1  = (const float*)d_in[2];
    const float* b1  = (const float*)d_in[3];
    const float* W2  = (const float*)d_in[4];
    const float* b2  = (const float*)d_in[5];
    const float* W3  = (const float*)d_in[6];
    const float* b3  = (const float*)d_in[7];
    const float* Wd1 = (const float*)d_in[8];
    const float* bd1 = (const float*)d_in[9];
    const float* Wd2 = (const float*)d_in[10];
    const float* bd2 = (const float*)d_in[11];
    float* out = (float*)d_out;

    float *bufA, *bufB;
    cudaGetSymbolAddress((void**)&bufA, g_bufA);
    cudaGetSymbolAddress((void**)&bufB, g_bufB);

    const int smem_conv  = (16384 + 16384) * (int)sizeof(float);          // 128 KB
    const int smem_dense = (16384 + 8192 + 16384) * (int)sizeof(float);   // 160 KB
    cudaFuncSetAttribute((const void*)conv_gemm_kernel,
                         cudaFuncAttributeMaxDynamicSharedMemorySize, smem_conv);
    cudaFuncSetAttribute((const void*)dense_kernel,
                         cudaFuncAttributeMaxDynamicSharedMemorySize, smem_dense);

    const int gblocks = (NN + 127) / 128;      // 391
    const int eblocks = (NE + 255) / 256;      // 3125
    const int nblocks = (NN + 255) / 256;      // 196
    const int wblocks = (NN * 32 + 255) / 256; // 6250

    // Preprocess: degrees, dinv, CSR
    pre_kernel<<<nblocks, 256>>>((const unsigned*)ei);
    convert_count_kernel<<<eblocks, 256>>>(ei);
    scan_kernel<<<1, 1024>>>();
    fill_kernel<<<eblocks, 256>>>();

    // Conv layer 1
    conv_gemm_kernel<<<gblocks, 512, smem_conv>>>(x, nullptr, W1, bufA);
    gather_kernel<<<wblocks, 256>>>(bufA, bufB);

    // Conv layer 2 (bias+relu of layer 1 fused into A-load)
    conv_gemm_kernel<<<gblocks, 512, smem_conv>>>(bufB, b1, W2, bufA);
    gather_kernel<<<wblocks, 256>>>(bufA, bufB);

    // Conv layer 3
    conv_gemm_kernel<<<gblocks, 512, smem_conv>>>(bufB, b2, W3, bufA);
    gather_kernel<<<wblocks, 256>>>(bufA, bufB);

    // Fused dense head
    dense_kernel<<<gblocks, 512, smem_dense>>>(bufB, b3, Wd1, bd1, Wd2, bd2, out);
}

// round 4
// speedup vs baseline: 1.3038x; 1.0294x over previous
#include <cuda_runtime.h>
#include <math.h>

#define NN 50000
#define NE 800000
#define HD 128
#define OD 64

typedef unsigned long long ull;

// Scratch (device globals: no allocation allowed in kernel_launch)
__device__ __align__(16) float g_bufA[NN * HD];
__device__ __align__(16) float g_bufB[NN * HD];
__device__ float g_dinv[NN];
__device__ int g_count[NN];
__device__ int g_rowstart[NN + 1];
__device__ int g_cursor[NN];
__device__ int g_src[NE];
__device__ int g_dst[NE];
__device__ __align__(16) int2 g_cedge[NE];   // (src, bitcast norm)
__device__ int g_is64;

// Packed fp32x2 FMA (Blackwell FFMA2, PTX-only path)
__device__ __forceinline__ void ffma2(ull& d, ull a, ull b) {
    asm("fma.rn.f32x2 %0, %1, %2, %0;" : "+l"(d) : "l"(a), "l"(b));
}

// ---------------------------------------------------------------------------
// Preprocess 1: zero degree counts + detect edge dtype (int64 LE has zero odd
// 32-bit words since all values < 50000).
// ---------------------------------------------------------------------------
__global__ void pre_kernel(const unsigned* __restrict__ p) {
    int i = blockIdx.x * blockDim.x + threadIdx.x;
    if (i < NN) g_count[i] = 0;
    if (i == 0) {
        int is64 = 1;
        for (int w = 1; w < 128; w += 2)
            if (p[w] != 0u) { is64 = 0; break; }
        g_is64 = is64;
    }
}

// Preprocess 2: convert edges to int32 + in-degree histogram.
__global__ void convert_count_kernel(const void* __restrict__ ei) {
    int e = blockIdx.x * blockDim.x + threadIdx.x;
    if (e >= NE) return;
    int s, d;
    if (g_is64) {
        const long long* p = (const long long*)ei;
        s = (int)p[e];
        d = (int)p[NE + e];
    } else {
        const int* p = (const int*)ei;
        s = p[e];
        d = p[NE + e];
    }
    g_src[e] = s;
    g_dst[e] = d;
    atomicAdd(&g_count[d], 1);
}

// Preprocess 3: single-block exclusive scan of counts -> rowstart/cursor,
// plus dinv = rsqrt(deg + 1) (self-loop included).
__global__ void scan_kernel() {
    __shared__ int partial[1024];
    const int tid = threadIdx.x;
    const int CH = (NN + 1023) / 1024;  // 49
    const int i0 = tid * CH;
    const int i1 = min(i0 + CH, NN);

    int sum = 0;
    for (int i = i0; i < i1; i++) sum += g_count[i];
    partial[tid] = sum;
    __syncthreads();
    for (int off = 1; off < 1024; off <<= 1) {
        int v = (tid >= off) ? partial[tid - off] : 0;
        __syncthreads();
        partial[tid] += v;
        __syncthreads();
    }
    int run = (tid > 0) ? partial[tid - 1] : 0;
    for (int i = i0; i < i1; i++) {
        g_rowstart[i] = run;
        g_cursor[i] = run;
        int c = g_count[i];
        run += c;
        g_dinv[i] = rsqrtf((float)c + 1.f);
    }
    if (tid == 0) g_rowstart[NN] = NE;
}

// Preprocess 4: bucket-fill CSR with packed (src, norm) records.
// dinv is ready (scan ran first), so the gather never touches dinv per edge.
__global__ void fill_kernel() {
    int e = blockIdx.x * blockDim.x + threadIdx.x;
    if (e >= NE) return;
    int s = g_src[e];
    int d = g_dst[e];
    int pos = atomicAdd(&g_cursor[d], 1);
    float nm = g_dinv[s] * g_dinv[d];
    g_cedge[pos] = make_int2(s, __float_as_int(nm));
}

// ---------------------------------------------------------------------------
// Conv GEMM: out = act(A) @ W, act = relu(.+inb) if inb.
// 512 threads, 128-row tile. k-pair packed FFMA2: W staged in smem as
// (W[2k][c], W[2k+1][c]) f32x2 pairs; A read as float2 over (2k, 2k+1).
// ---------------------------------------------------------------------------
__global__ void __launch_bounds__(512, 1)
conv_gemm_kernel(const float* __restrict__ A,
                 const float* __restrict__ inb,
                 const float* __restrict__ W,
                 float* __restrict__ out) {
    extern __shared__ float sm[];
    float* Wp  = sm;             // 64 kpairs * 128 cols * 2 = 16384 floats
    float* Ash = sm + 16384;     // 128 rows * 128 k
    const int tid = threadIdx.x;
    const int row0 = blockIdx.x * 128;

    // Stage W into pair layout: ull index kp*128 + c
    for (int i = tid; i < 4096; i += 512) {
        int k = i >> 5;           // source row
        int c4 = i & 31;          // float4 col group
        float4 v = ((const float4*)W)[i];
        float* base = Wp + (k >> 1) * 256 + c4 * 8 + (k & 1);
        base[0] = v.x; base[2] = v.y; base[4] = v.z; base[6] = v.w;
    }
    // Stage A tile (fused prev-layer bias+relu)
    for (int i = tid; i < 128 * 32; i += 512) {
        int r = i >> 5, q = i & 31;
        int grow = row0 + r;
        float4 v = make_float4(0.f, 0.f, 0.f, 0.f);
        if (grow < NN) {
            v = ((const float4*)A)[grow * 32 + q];
            if (inb) {
                const float4 b = ((const float4*)inb)[q];
                v.x = fmaxf(v.x + b.x, 0.f);
                v.y = fmaxf(v.y + b.y, 0.f);
                v.z = fmaxf(v.z + b.z, 0.f);
                v.w = fmaxf(v.w + b.w, 0.f);
            }
        }
        ((float4*)Ash)[i] = v;
    }
    __syncthreads();

    const ull* Wp2 = (const ull*)Wp;
    const int cx = tid & 15;
    const int ry = (tid >> 4) * 4;

    ull acc[4][8];
    #pragma unroll
    for (int r = 0; r < 4; r++)
        #pragma unroll
        for (int j = 0; j < 8; j++) acc[r][j] = 0ull;

    #pragma unroll 2
    for (int kp = 0; kp < 64; kp++) {
        ull w[8];
        #pragma unroll
        for (int j = 0; j < 8; j++) w[j] = Wp2[kp * 128 + cx + 16 * j];
        #pragma unroll
        for (int r = 0; r < 4; r++) {
            ull a2 = *(const ull*)(Ash + (ry + r) * 128 + kp * 2);
            #pragma unroll
            for (int j = 0; j < 8; j++) ffma2(acc[r][j], a2, w[j]);
        }
    }

    #pragma unroll
    for (int r = 0; r < 4; r++) {
        int grow = row0 + ry + r;
        if (grow >= NN) continue;
        #pragma unroll
        for (int j = 0; j < 8; j++) {
            float2 p = *(float2*)&acc[r][j];
            out[grow * HD + cx + 16 * j] = p.x + p.y;
        }
    }
}

// ---------------------------------------------------------------------------
// CSR gather aggregation: one warp per destination node, unrolled x4 with
// independent row loads (MLP=4). Edge records carry (src, norm) so the hot
// loop has no dependent scalar loads. Self-loop folded into init.
// ---------------------------------------------------------------------------
__global__ void gather_kernel(const float* __restrict__ t,
                              float* __restrict__ out) {
    int gid = blockIdx.x * blockDim.x + threadIdx.x;
    int d = gid >> 5;
    int lane = gid & 31;
    if (d >= NN) return;

    float dd = g_dinv[d];
    float4 acc = ((const float4*)(t + d * HD))[lane];
    float s2 = dd * dd;
    acc.x *= s2; acc.y *= s2; acc.z *= s2; acc.w *= s2;

    int j = g_rowstart[d];
    const int end = g_rowstart[d + 1];

    for (; j + 4 <= end; j += 4) {
        int2 e0 = g_cedge[j];
        int2 e1 = g_cedge[j + 1];
        int2 e2 = g_cedge[j + 2];
        int2 e3 = g_cedge[j + 3];
        float4 v0 = ((const float4*)(t + e0.x * HD))[lane];
        float4 v1 = ((const float4*)(t + e1.x * HD))[lane];
        float4 v2 = ((const float4*)(t + e2.x * HD))[lane];
        float4 v3 = ((const float4*)(t + e3.x * HD))[lane];
        float n0 = __int_as_float(e0.y);
        float n1 = __int_as_float(e1.y);
        float n2 = __int_as_float(e2.y);
        float n3 = __int_as_float(e3.y);
        acc.x = fmaf(v0.x, n0, acc.x);
        acc.y = fmaf(v0.y, n0, acc.y);
        acc.z = fmaf(v0.z, n0, acc.z);
        acc.w = fmaf(v0.w, n0, acc.w);
        acc.x = fmaf(v1.x, n1, acc.x);
        acc.y = fmaf(v1.y, n1, acc.y);
        acc.z = fmaf(v1.z, n1, acc.z);
        acc.w = fmaf(v1.w, n1, acc.w);
        acc.x = fmaf(v2.x, n2, acc.x);
        acc.y = fmaf(v2.y, n2, acc.y);
        acc.z = fmaf(v2.z, n2, acc.z);
        acc.w = fmaf(v2.w, n2, acc.w);
        acc.x = fmaf(v3.x, n3, acc.x);
        acc.y = fmaf(v3.y, n3, acc.y);
        acc.z = fmaf(v3.z, n3, acc.z);
        acc.w = fmaf(v3.w, n3, acc.w);
    }
    for (; j < end; j++) {
        int2 e0 = g_cedge[j];
        float n0 = __int_as_float(e0.y);
        float4 v0 = ((const float4*)(t + e0.x * HD))[lane];
        acc.x = fmaf(v0.x, n0, acc.x);
        acc.y = fmaf(v0.y, n0, acc.y);
        acc.z = fmaf(v0.z, n0, acc.z);
        acc.w = fmaf(v0.w, n0, acc.w);
    }
    ((float4*)(out + d * HD))[lane] = acc;
}

// ---------------------------------------------------------------------------
// Fused dense head: out = sigmoid( relu( relu(A+b3) @ Wd1 + bd1 ) @ Wd2 + bd2 )
// ---------------------------------------------------------------------------
__global__ void __launch_bounds__(512, 1)
dense_kernel(const float* __restrict__ A,
             const float* __restrict__ b3,
             const float* __restrict__ Wd1,
             const float* __restrict__ bd1,
             const float* __restrict__ Wd2,
             const float* __restrict__ bd2,
             float* __restrict__ out) {
    extern __shared__ float sm[];
    float* W1p = sm;             // 16384
    float* W2p = sm + 16384;     // 8192 (64 kpairs * 64 cols * 2)
    float* Ash = sm + 24576;     // 16384
    const int tid = threadIdx.x;
    const int row0 = blockIdx.x * 128;

    for (int i = tid; i < 4096; i += 512) {
        int k = i >> 5, c4 = i & 31;
        float4 v = ((const float4*)Wd1)[i];
        float* base = W1p + (k >> 1) * 256 + c4 * 8 + (k & 1);
        base[0] = v.x; base[2] = v.y; base[4] = v.z; base[6] = v.w;
    }
    for (int i = tid; i < 2048; i += 512) {
        int k = i >> 4, c4 = i & 15;
        float4 v = ((const float4*)Wd2)[i];
        float* base = W2p + (k >> 1) * 128 + c4 * 8 + (k & 1);
        base[0] = v.x; base[2] = v.y; base[4] = v.z; base[6] = v.w;
    }
    for (int i = tid; i < 128 * 32; i += 512) {
        int r = i >> 5, q = i & 31;
        int grow = row0 + r;
        float4 v = make_float4(0.f, 0.f, 0.f, 0.f);
        if (grow < NN) {
            v = ((const float4*)A)[grow * 32 + q];
            const float4 b = ((const float4*)b3)[q];
            v.x = fmaxf(v.x + b.x, 0.f);
            v.y = fmaxf(v.y + b.y, 0.f);
            v.z = fmaxf(v.z + b.z, 0.f);
            v.w = fmaxf(v.w + b.w, 0.f);
        }
        ((float4*)Ash)[i] = v;
    }
    __syncthreads();

    // ---- GEMM1: h1 = relu(A @ Wd1 + bd1) ----
    const ull* W1p2 = (const ull*)W1p;
    const int cx = tid & 15;
    const int ry = (tid >> 4) * 4;

    ull acc[4][8];
    #pragma unroll
    for (int r = 0; r < 4; r++)
        #pragma unroll
        for (int j = 0; j < 8; j++) acc[r][j] = 0ull;

    #pragma unroll 2
    for (int kp = 0; kp < 64; kp++) {
        ull w[8];
        #pragma unroll
        for (int j = 0; j < 8; j++) w[j] = W1p2[kp * 128 + cx + 16 * j];
        #pragma unroll
        for (int r = 0; r < 4; r++) {
            ull a2 = *(const ull*)(Ash + (ry + r) * 128 + kp * 2);
            #pragma unroll
            for (int j = 0; j < 8; j++) ffma2(acc[r][j], a2, w[j]);
        }
    }

    float h[4][8];
    #pragma unroll
    for (int r = 0; r < 4; r++)
        #pragma unroll
        for (int j = 0; j < 8; j++) {
            float2 p = *(float2*)&acc[r][j];
            h[r][j] = fmaxf(p.x + p.y + bd1[cx + 16 * j], 0.f);
        }

    __syncthreads();
    #pragma unroll
    for (int r = 0; r < 4; r++)
        #pragma unroll
        for (int j = 0; j < 8; j++)
            Ash[(ry + r) * 128 + cx + 16 * j] = h[r][j];
    __syncthreads();

    // ---- GEMM2: out = sigmoid(h1 @ Wd2 + bd2) ----
    const ull* W2p2 = (const ull*)W2p;
    const int cx2 = tid & 7;            // cols = cx2 + 8j
    const int ry2 = (tid >> 3) * 2;     // 2 rows per thread

    ull acc2[2][8];
    #pragma unroll
    for (int r = 0; r < 2; r++)
        #pragma unroll
        for (int j = 0; j < 8; j++) acc2[r][j] = 0ull;

    #pragma unroll 2
    for (int kp = 0; kp < 64; kp++) {
        ull w[8];
        #pragma unroll
        for (int j = 0; j < 8; j++) w[j] = W2p2[kp * 64 + cx2 + 8 * j];
        #pragma unroll
        for (int r = 0; r < 2; r++) {
            ull a2 = *(const ull*)(Ash + (ry2 + r) * 128 + kp * 2);
            #pragma unroll
            for (int j = 0; j < 8; j++) ffma2(acc2[r][j], a2, w[j]);
        }
    }

    #pragma unroll
    for (int r = 0; r < 2; r++) {
        int grow = row0 + ry2 + r;
        if (grow >= NN) continue;
        #pragma unroll
        for (int j = 0; j < 8; j++) {
            float2 p = *(float2*)&acc2[r][j];
            float v = p.x + p.y + bd2[cx2 + 8 * j];
            out[grow * OD + cx2 + 8 * j] = 1.f / (1.f + __expf(-v));
        }
    }
}

// ---------------------------------------------------------------------------
extern "C" void kernel_launch(void* const* d_in, const int* in_sizes, int n_in,
                              void* d_out, int out_size) {
    const float* x   = (const float*)d_in[0];
    const void*  ei  = d_in[1];
    const float* W1  = (const float*)d_in[2];
    const float* b1  = (const float*)d_in[3];
    const float* W2  = (const float*)d_in[4];
    const float* b2  = (const float*)d_in[5];
    const float* W3  = (const float*)d_in[6];
    const float* b3  = (const float*)d_in[7];
    const float* Wd1 = (const float*)d_in[8];
    const float* bd1 = (const float*)d_in[9];
    const float* Wd2 = (const float*)d_in[10];
    const float* bd2 = (const float*)d_in[11];
    float* out = (float*)d_out;

    float *bufA, *bufB;
    cudaGetSymbolAddress((void**)&bufA, g_bufA);
    cudaGetSymbolAddress((void**)&bufB, g_bufB);

    const int smem_conv  = (16384 + 16384) * (int)sizeof(float);          // 128 KB
    const int smem_dense = (16384 + 8192 + 16384) * (int)sizeof(float);   // 160 KB
    cudaFuncSetAttribute((const void*)conv_gemm_kernel,
                         cudaFuncAttributeMaxDynamicSharedMemorySize, smem_conv);
    cudaFuncSetAttribute((const void*)dense_kernel,
                         cudaFuncAttributeMaxDynamicSharedMemorySize, smem_dense);

    const int gblocks = (NN + 127) / 128;      // 391
    const int eblocks = (NE + 255) / 256;      // 3125
    const int nblocks = (NN + 255) / 256;      // 196
    const int wblocks = (NN * 32 + 255) / 256; // 6250

    // Preprocess: degrees, dinv, CSR with fused per-edge norms
    pre_kernel<<<nblocks, 256>>>((const unsigned*)ei);
    convert_count_kernel<<<eblocks, 256>>>(ei);
    scan_kernel<<<1, 1024>>>();
    fill_kernel<<<eblocks, 256>>>();

    // Conv layer 1
    conv_gemm_kernel<<<gblocks, 512, smem_conv>>>(x, nullptr, W1, bufA);
    gather_kernel<<<wblocks, 256>>>(bufA, bufB);

    // Conv layer 2 (bias+relu of layer 1 fused into A-load)
    conv_gemm_kernel<<<gblocks, 512, smem_conv>>>(bufB, b1, W2, bufA);
    gather_kernel<<<wblocks, 256>>>(bufA, bufB);

    // Conv layer 3
    conv_gemm_kernel<<<gblocks, 512, smem_conv>>>(bufB, b2, W3, bufA);
    gather_kernel<<<wblocks, 256>>>(bufA, bufB);

    // Fused dense head
    dense_kernel<<<gblocks, 512, smem_dense>>>(bufB, b3, Wd1, bd1, Wd2, bd2, out);
}